// round 2
// baseline (speedup 1.0000x reference)
#include <cuda_runtime.h>
#include <cstdint>

// ---------------- problem constants ----------------
#define BATCH   2
#define SEQ     2048
#define TOK     (BATCH * SEQ)        // 4096
#define DM      768                  // d_model
#define DI      1536                 // d_inner
#define DI2     (2 * DI)             // 3072
#define NSTATE  16
#define NX      33                   // 1 + 2*NSTATE
#define DCONV   4

// ---------------- scratch (static device globals; no runtime alloc) --------
__device__ float g_xn  [TOK * DM];            // layernorm output
__device__ float g_xz  [2ll * TOK * DI2];     // per-dir in-proj output
__device__ float g_xc  [2ll * TOK * DI];      // per-dir conv+silu output
__device__ float g_bcdt[2ll * TOK * NX];      // per-dir xc @ xw
__device__ float g_dt  [2ll * TOK * DI];      // softplus(dt)
__device__ float g_u   [2ll * TOK * DI];      // dt * xc
__device__ float g_ys  [2ll * TOK * DI];      // scan output
__device__ float g_g   [2ll * TOK * DI];      // gated activation (pre out-proj)
__device__ float g_yp  [2ll * TOK * DM];      // per-dir out-proj

// ---------------- layernorm ----------------
__device__ __forceinline__ float block_sum(float v, float* sh) {
    int lane = threadIdx.x & 31, w = threadIdx.x >> 5;
    #pragma unroll
    for (int o = 16; o; o >>= 1) v += __shfl_xor_sync(0xffffffffu, v, o);
    if (lane == 0) sh[w] = v;
    __syncthreads();
    float r;
    if (w == 0) {
        float x = (lane < 8) ? sh[lane] : 0.f;
        #pragma unroll
        for (int o = 4; o; o >>= 1) x += __shfl_xor_sync(0xffffffffu, x, o);
        if (lane == 0) sh[0] = x;
    }
    __syncthreads();
    r = sh[0];
    __syncthreads();
    return r;
}

__global__ __launch_bounds__(256) void ln_kernel(
    const float* __restrict__ x, const float* __restrict__ gam,
    const float* __restrict__ bet, float* __restrict__ xn)
{
    __shared__ float sh[8];
    int tok = blockIdx.x;
    const float* xr = x + (size_t)tok * DM;
    int tid = threadIdx.x;
    float v0 = xr[tid], v1 = xr[tid + 256], v2 = xr[tid + 512];
    float s = block_sum(v0 + v1 + v2, sh);
    float mu = s * (1.0f / DM);
    float d0 = v0 - mu, d1 = v1 - mu, d2 = v2 - mu;
    float vs = block_sum(d0 * d0 + d1 * d1 + d2 * d2, sh);
    float inv = rsqrtf(vs * (1.0f / DM) + 1e-5f);
    float* orow = xn + (size_t)tok * DM;
    orow[tid]        = d0 * inv * gam[tid]        + bet[tid];
    orow[tid + 256]  = d1 * inv * gam[tid + 256]  + bet[tid + 256];
    orow[tid + 512]  = d2 * inv * gam[tid + 512]  + bet[tid + 512];
}

// ---------------- fp32 SGEMM (128x128x8 tiling, 8x8 per thread) ----------
// C[dir] = A (optionally per-dir, optionally time-flipped when dir==1) @ B[dir]
#define BM 128
#define BN 128
#define BKK 8
#define TM 8
#define TN 8

__global__ __launch_bounds__(256) void sgemm_k(
    const float* __restrict__ A, const float* __restrict__ B0,
    const float* __restrict__ B1, float* __restrict__ C,
    int M, int N, int K, int aPerDir, int flipA)
{
    int dir = blockIdx.z;
    const float* Bp = dir ? B1 : B0;
    const float* Ap = A + (aPerDir ? (size_t)dir * M * K : 0);
    float* Cp = C + (size_t)dir * (size_t)M * N;

    __shared__ float As[BKK][BM];
    __shared__ float Bs[BKK][BN];

    int tid = threadIdx.x;
    int rowBase = blockIdx.y * BM;
    int colBase = blockIdx.x * BN;
    int tx = tid & 15;     // 0..15 col group
    int ty = tid >> 4;     // 0..15 row group

    float acc[TM][TN];
    #pragma unroll
    for (int i = 0; i < TM; i++)
        #pragma unroll
        for (int j = 0; j < TN; j++) acc[i][j] = 0.f;

    int aRow = tid >> 1;
    int aCol = (tid & 1) * 4;
    int bRow = tid >> 5;
    int bCol = (tid & 31) * 4;

    int gRow = rowBase + aRow;
    if (flipA && dir) gRow ^= (SEQ - 1);   // flip l within its batch (M=4096=2*2048)
    const float* aSrc = Ap + (size_t)gRow * K + aCol;
    const float* bSrc = Bp + (size_t)bRow * N + colBase + bCol;

    for (int kt = 0; kt < K; kt += BKK) {
        float4 av = *reinterpret_cast<const float4*>(aSrc + kt);
        float4 bv = *reinterpret_cast<const float4*>(bSrc + (size_t)kt * N);
        As[aCol + 0][aRow] = av.x;
        As[aCol + 1][aRow] = av.y;
        As[aCol + 2][aRow] = av.z;
        As[aCol + 3][aRow] = av.w;
        *reinterpret_cast<float4*>(&Bs[bRow][bCol]) = bv;
        __syncthreads();
        #pragma unroll
        for (int k = 0; k < BKK; ++k) {
            float a[TM], b[TN];
            #pragma unroll
            for (int i = 0; i < TM; i++) a[i] = As[k][ty * TM + i];
            #pragma unroll
            for (int j = 0; j < TN; j++) b[j] = Bs[k][tx * TN + j];
            #pragma unroll
            for (int i = 0; i < TM; i++)
                #pragma unroll
                for (int j = 0; j < TN; j++)
                    acc[i][j] = fmaf(a[i], b[j], acc[i][j]);
        }
        __syncthreads();
    }
    #pragma unroll
    for (int i = 0; i < TM; i++) {
        int r = rowBase + ty * TM + i;
        float* crow = Cp + (size_t)r * N + colBase + tx * TN;
        float4 v0 = make_float4(acc[i][0], acc[i][1], acc[i][2], acc[i][3]);
        float4 v1 = make_float4(acc[i][4], acc[i][5], acc[i][6], acc[i][7]);
        reinterpret_cast<float4*>(crow)[0] = v0;
        reinterpret_cast<float4*>(crow)[1] = v1;
    }
}

// ---------------- depthwise causal conv (k=4) + bias + SiLU --------------
__global__ __launch_bounds__(256) void conv_silu_kernel(
    const float* __restrict__ xz, const float* __restrict__ cw0,
    const float* __restrict__ cw1, const float* __restrict__ cb0,
    const float* __restrict__ cb1, float* __restrict__ xc)
{
    int dir = blockIdx.z;
    int idx = blockIdx.x * blockDim.x + threadIdx.x;   // tok*DI + d
    if (idx >= TOK * DI) return;
    int tok = idx / DI;
    int d   = idx - tok * DI;
    int l   = tok & (SEQ - 1);
    const float* cw = (dir ? cw1 : cw0) + d * DCONV;
    float acc = (dir ? cb1 : cb0)[d];
    const float* xzp = xz + (size_t)dir * TOK * DI2 + (size_t)tok * DI2 + d;
    #pragma unroll
    for (int j = 0; j < DCONV; j++) {
        int lo = l - (DCONV - 1) + j;
        if (lo >= 0) acc = fmaf(cw[j], xzp[(long)(j - (DCONV - 1)) * DI2], acc);
    }
    float sg = 1.f / (1.f + __expf(-acc));
    xc[(size_t)dir * TOK * DI + idx] = acc * sg;
}

// ---------------- bcdt = xc @ xw   (K=1536, N=33; warp per token) --------
__global__ __launch_bounds__(256) void bcdt_kernel(
    const float* __restrict__ xc, const float* __restrict__ xw0,
    const float* __restrict__ xw1, float* __restrict__ bcdt)
{
    int dir = blockIdx.z;
    int warp = threadIdx.x >> 5;
    int lane = threadIdx.x & 31;
    int tok = blockIdx.x * 8 + warp;
    const float* xw = dir ? xw1 : xw0;
    const float* xr = xc + (size_t)dir * TOK * DI + (size_t)tok * DI;
    float acc = 0.f, acc32 = 0.f;
    for (int k = 0; k < DI; k += 4) {
        float4 xv = *reinterpret_cast<const float4*>(xr + k);
        const float* wr = xw + (size_t)k * NX;
        acc = fmaf(xv.x, wr[lane],          acc);
        acc = fmaf(xv.y, wr[NX + lane],     acc);
        acc = fmaf(xv.z, wr[2 * NX + lane], acc);
        acc = fmaf(xv.w, wr[3 * NX + lane], acc);
        if (lane == 0) {
            acc32 = fmaf(xv.x, wr[32], acc32);
            acc32 = fmaf(xv.y, wr[NX + 32], acc32);
            acc32 = fmaf(xv.z, wr[2 * NX + 32], acc32);
            acc32 = fmaf(xv.w, wr[3 * NX + 32], acc32);
        }
    }
    float* orow = bcdt + ((size_t)dir * TOK + tok) * NX;
    orow[lane] = acc;
    if (lane == 0) orow[32] = acc32;
}

// ---------------- dt = softplus(dt_raw*dtw+dtb);  u = dt*xc --------------
__global__ __launch_bounds__(256) void dtu_kernel(
    const float* __restrict__ bcdt, const float* __restrict__ xc,
    const float* __restrict__ dtw0, const float* __restrict__ dtw1,
    const float* __restrict__ dtb0, const float* __restrict__ dtb1,
    float* __restrict__ dt, float* __restrict__ u)
{
    int dir = blockIdx.z;
    int idx = blockIdx.x * blockDim.x + threadIdx.x;
    if (idx >= TOK * DI) return;
    int tok = idx / DI;
    int d   = idx - tok * DI;
    float draw = bcdt[((size_t)dir * TOK + tok) * NX];
    float pre = fmaf(draw, (dir ? dtw1 : dtw0)[d], (dir ? dtb1 : dtb0)[d]);
    float dtv = (pre > 20.f) ? pre : log1pf(expf(pre));
    size_t o = (size_t)dir * TOK * DI + idx;
    dt[o] = dtv;
    u[o]  = dtv * xc[o];
}

// ---------------- selective scan: warp handles 2 (b,d) channels ----------
__global__ __launch_bounds__(256) void scan_kernel(
    const float* __restrict__ bcdt, const float* __restrict__ dt,
    const float* __restrict__ u, const float* __restrict__ Alog0,
    const float* __restrict__ Alog1, float* __restrict__ ys)
{
    int wg   = (blockIdx.x * blockDim.x + threadIdx.x) >> 5;  // 0..3071
    int lane = threadIdx.x & 31;
    int dir  = wg / 1536;
    int rem  = wg - dir * 1536;
    int b    = rem / 768;
    int wp   = rem - b * 768;
    int half = lane >> 4;
    int s    = lane & 15;
    int d    = wp * 2 + half;

    const float* Alog = dir ? Alog1 : Alog0;
    float al = Alog[d * NSTATE + s];
    al = fminf(fmaxf(al, -6.f), 6.f);
    float Aval = -__expf(al);

    size_t tokBase = (size_t)dir * TOK + (size_t)b * SEQ;
    const float* dtp  = dt   + tokBase * DI + d;
    const float* up   = u    + tokBase * DI + d;
    const float* rowp = bcdt + tokBase * NX;
    float* ysp        = ys   + tokBase * DI + d;

    float h = 0.f;
    float dtv = *dtp, uv = *up;
    float Bv = rowp[1 + s], Cv = rowp[17 + s];

    for (int t = 0; t < SEQ; ++t) {
        float a = __expf(dtv * Aval);
        float hb = fmaf(a, h, uv * Bv);
        hb = fminf(fmaxf(hb, -10000.f), 10000.f);
        h = hb;
        float p = h * Cv;
        if (t < SEQ - 1) {               // prefetch t+1 while reduction runs
            dtp += DI; up += DI; rowp += NX;
            dtv = *dtp; uv = *up;
            Bv = rowp[1 + s]; Cv = rowp[17 + s];
        }
        p += __shfl_xor_sync(0xffffffffu, p, 8);
        p += __shfl_xor_sync(0xffffffffu, p, 4);
        p += __shfl_xor_sync(0xffffffffu, p, 2);
        p += __shfl_xor_sync(0xffffffffu, p, 1);
        if (s == 0) *ysp = p;
        ysp += DI;
    }
}

// ---------------- gate: g = (ys + xc*Dp) * silu(z) -----------------------
__global__ __launch_bounds__(256) void gate_kernel(
    const float* __restrict__ ys, const float* __restrict__ xc,
    const float* __restrict__ xz, const float* __restrict__ Dp0,
    const float* __restrict__ Dp1, float* __restrict__ g)
{
    int dir = blockIdx.z;
    int idx = blockIdx.x * blockDim.x + threadIdx.x;
    if (idx >= TOK * DI) return;
    int tok = idx / DI;
    int d   = idx - tok * DI;
    size_t o = (size_t)dir * TOK * DI + idx;
    float z = xz[(size_t)dir * TOK * DI2 + (size_t)tok * DI2 + DI + d];
    float sz = z / (1.f + __expf(-z));
    float y = fmaf(xc[o], (dir ? Dp1 : Dp0)[d], ys[o]);
    g[o] = y * sz;
}

// ---------------- combine: out = a*yf + (1-a)*flip(yb) + x ---------------
__global__ __launch_bounds__(256) void combine_kernel(
    const float* __restrict__ x, const float* __restrict__ alpha,
    const float* __restrict__ yp, float* __restrict__ out)
{
    int idx = blockIdx.x * blockDim.x + threadIdx.x;   // tok*DM + m
    if (idx >= TOK * DM) return;
    int tok = idx / DM;
    int m   = idx - tok * DM;
    float a = 1.f / (1.f + __expf(-alpha[0]));
    int tokb = tok ^ (SEQ - 1);          // flip l within batch
    float yf = yp[idx];
    float yb = yp[(size_t)TOK * DM + (size_t)tokb * DM + m];
    out[idx] = fmaf(a, yf, fmaf(1.f - a, yb, x[idx]));
}

// ---------------- launch --------------------------------------------------
extern "C" void kernel_launch(void* const* d_in, const int* in_sizes, int n_in,
                              void* d_out, int out_size)
{
    const float* x     = (const float*)d_in[0];
    const float* ln_g  = (const float*)d_in[1];
    const float* ln_b  = (const float*)d_in[2];
    const float* alpha = (const float*)d_in[3];
    const float* f_inw  = (const float*)d_in[4];
    const float* f_cw   = (const float*)d_in[5];
    const float* f_cb   = (const float*)d_in[6];
    const float* f_xw   = (const float*)d_in[7];
    const float* f_dtw  = (const float*)d_in[8];
    const float* f_dtb  = (const float*)d_in[9];
    const float* f_Alog = (const float*)d_in[10];
    const float* f_D    = (const float*)d_in[11];
    const float* f_outw = (const float*)d_in[12];
    const float* b_inw  = (const float*)d_in[13];
    const float* b_cw   = (const float*)d_in[14];
    const float* b_cb   = (const float*)d_in[15];
    const float* b_xw   = (const float*)d_in[16];
    const float* b_dtw  = (const float*)d_in[17];
    const float* b_dtb  = (const float*)d_in[18];
    const float* b_Alog = (const float*)d_in[19];
    const float* b_D    = (const float*)d_in[20];
    const float* b_outw = (const float*)d_in[21];
    float* out = (float*)d_out;

    float *xn, *xz, *xc, *bcdt, *dt, *u, *ys, *gg, *yp;
    cudaGetSymbolAddress((void**)&xn,   g_xn);
    cudaGetSymbolAddress((void**)&xz,   g_xz);
    cudaGetSymbolAddress((void**)&xc,   g_xc);
    cudaGetSymbolAddress((void**)&bcdt, g_bcdt);
    cudaGetSymbolAddress((void**)&dt,   g_dt);
    cudaGetSymbolAddress((void**)&u,    g_u);
    cudaGetSymbolAddress((void**)&ys,   g_ys);
    cudaGetSymbolAddress((void**)&gg,   g_g);
    cudaGetSymbolAddress((void**)&yp,   g_yp);

    // 1) layernorm
    ln_kernel<<<TOK, 256>>>(x, ln_g, ln_b, xn);

    // 2) in-proj GEMM (both dirs; dir 1 reads time-flipped xn)
    sgemm_k<<<dim3(DI2 / BN, TOK / BM, 2), 256>>>(
        xn, f_inw, b_inw, xz, TOK, DI2, DM, /*aPerDir=*/0, /*flipA=*/1);

    // 3) depthwise conv + SiLU
    conv_silu_kernel<<<dim3((TOK * DI) / 256, 1, 2), 256>>>(
        xz, f_cw, b_cw, f_cb, b_cb, xc);

    // 4) bcdt = xc @ xw
    bcdt_kernel<<<dim3(TOK / 8, 1, 2), 256>>>(xc, f_xw, b_xw, bcdt);

    // 5) dt/u precompute
    dtu_kernel<<<dim3((TOK * DI) / 256, 1, 2), 256>>>(
        bcdt, xc, f_dtw, b_dtw, f_dtb, b_dtb, dt, u);

    // 6) selective scan (both dirs in one grid)
    scan_kernel<<<384, 256>>>(bcdt, dt, u, f_Alog, b_Alog, ys);

    // 7) gate
    gate_kernel<<<dim3((TOK * DI) / 256, 1, 2), 256>>>(
        ys, xc, xz, f_D, b_D, gg);

    // 8) out-proj GEMM
    sgemm_k<<<dim3(DM / BN, TOK / BM, 2), 256>>>(
        gg, f_outw, b_outw, yp, TOK, DM, DI, /*aPerDir=*/1, /*flipA=*/0);

    // 9) combine + residual
    combine_kernel<<<(TOK * DM) / 256, 256>>>(x, alpha, yp, out);
}

// round 4
// speedup vs baseline: 1.6590x; 1.6590x over previous
#include <cuda_runtime.h>
#include <cuda_bf16.h>
#include <cstdint>

// ---------------- problem constants ----------------
#define BATCH   2
#define SEQ     2048
#define TOK     (BATCH * SEQ)        // 4096
#define DM      768                  // d_model
#define DI      1536                 // d_inner
#define DI2     (2 * DI)             // 3072
#define NSTATE  16
#define NX      33                   // 1 + 2*NSTATE
#define DCONV   4

typedef __nv_bfloat16 bf16;

// ---------------- scratch (static device globals) --------
__device__ __align__(16) bf16  g_xn_h [TOK * DM];
__device__ __align__(16) bf16  g_xn_l [TOK * DM];
__device__ __align__(16) bf16  g_win_h[2ll * DI2 * DM];   // [dir][N=3072][K=768]
__device__ __align__(16) bf16  g_win_l[2ll * DI2 * DM];
__device__ __align__(16) bf16  g_wout_h[2ll * DM * DI];   // [dir][N=768][K=1536]
__device__ __align__(16) bf16  g_wout_l[2ll * DM * DI];
__device__ __align__(16) bf16  g_g_h [2ll * TOK * DI];
__device__ __align__(16) bf16  g_g_l [2ll * TOK * DI];
__device__ float g_xz  [2ll * TOK * DI2];
__device__ float g_xc  [2ll * TOK * DI];
__device__ float g_bcdt[2ll * TOK * NX];
__device__ float g_dt  [2ll * TOK * DI];
__device__ float g_u   [2ll * TOK * DI];
__device__ float g_ys  [2ll * TOK * DI];
__device__ float g_yp  [2ll * TOK * DM];

// ================= helpers =================
__device__ __forceinline__ uint32_t s2u(const void* p) {
    uint32_t a;
    asm("{ .reg .u64 t; cvta.to.shared.u64 t, %1; cvt.u32.u64 %0, t; }"
        : "=r"(a) : "l"(p));
    return a;
}
__device__ __forceinline__ uint32_t swz(uint32_t off) {
    return off ^ ((off >> 3) & 0x70);
}
__device__ __forceinline__ void cpasync16(uint32_t dst, const void* src) {
    asm volatile("cp.async.cg.shared.global [%0], [%1], 16;" :: "r"(dst), "l"(src) : "memory");
}
#define CP_COMMIT() asm volatile("cp.async.commit_group;" ::: "memory")
#define CP_WAIT0()  asm volatile("cp.async.wait_group 0;" ::: "memory")

__device__ __forceinline__ void ldsm4(uint32_t* r, uint32_t addr) {
    asm volatile("ldmatrix.sync.aligned.m8n8.x4.shared.b16 {%0,%1,%2,%3}, [%4];"
                 : "=r"(r[0]), "=r"(r[1]), "=r"(r[2]), "=r"(r[3]) : "r"(addr));
}
__device__ __forceinline__ void mma16816(float* c, const uint32_t* a,
                                         uint32_t b0, uint32_t b1) {
    asm volatile(
        "mma.sync.aligned.m16n8k16.row.col.f32.bf16.bf16.f32 "
        "{%0,%1,%2,%3}, {%4,%5,%6,%7}, {%8,%9}, {%0,%1,%2,%3};"
        : "+f"(c[0]), "+f"(c[1]), "+f"(c[2]), "+f"(c[3])
        : "r"(a[0]), "r"(a[1]), "r"(a[2]), "r"(a[3]), "r"(b0), "r"(b1));
}

// ================= mma.sync GEMM (bf16x3 split precision) =================
// C[dir][M][N] (fp32) = A(hi+lo)[M][K] @ B(hi+lo)[dir][N][K]^T
// 128x128 tile, K chunk 64, cp.async double-buffered, 8 warps (4M x 2N).
#define BK 64
#define TILE_B 16384                 // 128 rows x 128 bytes
#define STAGE_B (4 * TILE_B)         // Ah, Al, Bh, Bl

__global__ __launch_bounds__(256, 1)
void mma_gemm(const bf16* __restrict__ Ah, const bf16* __restrict__ Al,
              const bf16* __restrict__ Bh, const bf16* __restrict__ Bl,
              float* __restrict__ C, int M, int N, int K, int aPerDir, int flipA)
{
    extern __shared__ __align__(1024) char smem[];
    const int dir   = blockIdx.z;
    const int mBase = blockIdx.y * 128;
    const int nBase = blockIdx.x * 128;
    const uint32_t sb = s2u(smem);
    const int tid = threadIdx.x, wid = tid >> 5, lane = tid & 31;
    const int wm = wid & 3, wn = wid >> 2;

    const bf16* Ahp = Ah + (aPerDir ? (size_t)dir * M * K : 0);
    const bf16* Alp = Al + (aPerDir ? (size_t)dir * M * K : 0);
    const bf16* Bhp = Bh + (size_t)dir * (size_t)N * K;
    const bf16* Blp = Bl + (size_t)dir * (size_t)N * K;

    const int CK = K / BK;

    float acc[2][8][4];
    #pragma unroll
    for (int i = 0; i < 2; i++)
        #pragma unroll
        for (int j = 0; j < 8; j++)
            #pragma unroll
            for (int q = 0; q < 4; q++) acc[i][j][q] = 0.f;

    auto issue = [&](int c, int st) {
        const int k0 = c * BK;
        #pragma unroll
        for (int i = 0; i < 16; ++i) {
            int q     = tid + 256 * i;
            int which = q >> 10;            // 0 Ah, 1 Al, 2 Bh, 3 Bl
            int t     = q & 1023;
            int row   = t >> 3;
            int kb    = t & 7;
            const bf16* src;
            if (which < 2) {
                int grow = mBase + row;
                if (flipA && dir) grow ^= (SEQ - 1);
                src = (which ? Alp : Ahp) + (size_t)grow * K + k0 + kb * 8;
            } else {
                src = ((which == 3) ? Blp : Bhp) + (size_t)(nBase + row) * K + k0 + kb * 8;
            }
            uint32_t dst = sb + st * STAGE_B + which * TILE_B +
                           swz((uint32_t)(row * 128 + kb * 16));
            cpasync16(dst, src);
        }
        CP_COMMIT();
    };

    issue(0, 0);

    const int g  = lane >> 3;    // 8x8-tile group 0..3
    const int lr = lane & 7;

    for (int c = 0; c < CK; ++c) {
        CP_WAIT0();
        __syncthreads();
        if (c + 1 < CK) issue(c + 1, (c + 1) & 1);

        const uint32_t tb = sb + (c & 1) * STAGE_B;
        #pragma unroll
        for (int ks = 0; ks < 4; ++ks) {
            const int kByte = ks * 32 + (g >> 1) * 16;
            uint32_t bh[4][4], bl[4][4];
            #pragma unroll
            for (int j = 0; j < 4; ++j) {
                int row = wn * 64 + j * 16 + (g & 1) * 8 + lr;
                uint32_t off = swz((uint32_t)(row * 128 + kByte));
                ldsm4(bh[j], tb + 2 * TILE_B + off);
                ldsm4(bl[j], tb + 3 * TILE_B + off);
            }
            #pragma unroll
            for (int i = 0; i < 2; ++i) {
                int row = wm * 32 + i * 16 + (g & 1) * 8 + lr;
                uint32_t off = swz((uint32_t)(row * 128 + kByte));
                uint32_t ah[4], al[4];
                ldsm4(ah, tb + off);
                ldsm4(al, tb + TILE_B + off);
                #pragma unroll
                for (int j = 0; j < 4; ++j) {
                    mma16816(acc[i][2*j],   ah, bh[j][0], bh[j][2]);
                    mma16816(acc[i][2*j+1], ah, bh[j][1], bh[j][3]);
                    mma16816(acc[i][2*j],   ah, bl[j][0], bl[j][2]);
                    mma16816(acc[i][2*j+1], ah, bl[j][1], bl[j][3]);
                    mma16816(acc[i][2*j],   al, bh[j][0], bh[j][2]);
                    mma16816(acc[i][2*j+1], al, bh[j][1], bh[j][3]);
                }
            }
        }
        __syncthreads();
    }

    // epilogue: direct STG (fragment layout: row = lane/4 (+8), col = (lane%4)*2)
    float* Cp = C + (size_t)dir * (size_t)M * N;
    #pragma unroll
    for (int i = 0; i < 2; ++i) {
        int r0 = mBase + wm * 32 + i * 16 + (lane >> 2);
        #pragma unroll
        for (int j = 0; j < 8; ++j) {
            int col = nBase + wn * 64 + j * 8 + (lane & 3) * 2;
            float2 v0 = make_float2(acc[i][j][0], acc[i][j][1]);
            float2 v1 = make_float2(acc[i][j][2], acc[i][j][3]);
            *reinterpret_cast<float2*>(Cp + (size_t)r0 * N + col)       = v0;
            *reinterpret_cast<float2*>(Cp + (size_t)(r0 + 8) * N + col) = v1;
        }
    }
}

// ================= layernorm -> bf16 hi/lo =================
__device__ __forceinline__ float block_sum(float v, float* sh) {
    int lane = threadIdx.x & 31, w = threadIdx.x >> 5;
    #pragma unroll
    for (int o = 16; o; o >>= 1) v += __shfl_xor_sync(0xffffffffu, v, o);
    if (lane == 0) sh[w] = v;
    __syncthreads();
    if (w == 0) {
        float x = (lane < 8) ? sh[lane] : 0.f;
        #pragma unroll
        for (int o = 4; o; o >>= 1) x += __shfl_xor_sync(0xffffffffu, x, o);
        if (lane == 0) sh[0] = x;
    }
    __syncthreads();
    float r = sh[0];
    __syncthreads();
    return r;
}

__global__ __launch_bounds__(256) void ln_kernel(
    const float* __restrict__ x, const float* __restrict__ gam,
    const float* __restrict__ bet, bf16* __restrict__ xh, bf16* __restrict__ xl)
{
    __shared__ float sh[8];
    int tok = blockIdx.x;
    const float* xr = x + (size_t)tok * DM;
    int tid = threadIdx.x;
    float v0 = xr[tid], v1 = xr[tid + 256], v2 = xr[tid + 512];
    float s = block_sum(v0 + v1 + v2, sh);
    float mu = s * (1.0f / DM);
    float d0 = v0 - mu, d1 = v1 - mu, d2 = v2 - mu;
    float vs = block_sum(d0 * d0 + d1 * d1 + d2 * d2, sh);
    float inv = rsqrtf(vs * (1.0f / DM) + 1e-5f);
    size_t ob = (size_t)tok * DM;
    #pragma unroll
    for (int p = 0; p < 3; ++p) {
        int i = tid + p * 256;
        float d = (p == 0 ? d0 : p == 1 ? d1 : d2);
        float val = d * inv * gam[i] + bet[i];
        bf16 h = __float2bfloat16(val);
        xh[ob + i] = h;
        xl[ob + i] = __float2bfloat16(val - __bfloat162float(h));
    }
}

// ================= weight transpose + bf16 split =================
// w: [K][N] fp32 -> th/tl: [dir][N][K] bf16
__global__ void wsplit_kernel(const float* __restrict__ w0, const float* __restrict__ w1,
                              bf16* __restrict__ th, bf16* __restrict__ tl, int K, int N)
{
    __shared__ float t[32][33];
    int dir = blockIdx.z;
    const float* w = dir ? w1 : w0;
    int k0 = blockIdx.y * 32, n0 = blockIdx.x * 32;
    int tx = threadIdx.x, ty = threadIdx.y;
    #pragma unroll
    for (int i = 0; i < 4; ++i)
        t[ty + 8 * i][tx] = w[(size_t)(k0 + ty + 8 * i) * N + n0 + tx];
    __syncthreads();
    bf16* thp = th + (size_t)dir * N * K;
    bf16* tlp = tl + (size_t)dir * N * K;
    #pragma unroll
    for (int i = 0; i < 4; ++i) {
        int n = n0 + ty + 8 * i, k = k0 + tx;
        float v = t[tx][ty + 8 * i];
        bf16 h = __float2bfloat16(v);
        thp[(size_t)n * K + k] = h;
        tlp[(size_t)n * K + k] = __float2bfloat16(v - __bfloat162float(h));
    }
}

// ================= depthwise causal conv (k=4) + bias + SiLU =================
__global__ __launch_bounds__(256) void conv_silu_kernel(
    const float* __restrict__ xz, const float* __restrict__ cw0,
    const float* __restrict__ cw1, const float* __restrict__ cb0,
    const float* __restrict__ cb1, float* __restrict__ xc)
{
    int dir = blockIdx.z;
    int idx = blockIdx.x * blockDim.x + threadIdx.x;
    if (idx >= TOK * DI) return;
    int tok = idx / DI;
    int d   = idx - tok * DI;
    int l   = tok & (SEQ - 1);
    const float* cw = (dir ? cw1 : cw0) + d * DCONV;
    float acc = (dir ? cb1 : cb0)[d];
    const float* xzp = xz + (size_t)dir * TOK * DI2 + (size_t)tok * DI2 + d;
    #pragma unroll
    for (int j = 0; j < DCONV; j++) {
        int lo = l - (DCONV - 1) + j;
        if (lo >= 0) acc = fmaf(cw[j], xzp[(long)(j - (DCONV - 1)) * DI2], acc);
    }
    float sg = 1.f / (1.f + __expf(-acc));
    xc[(size_t)dir * TOK * DI + idx] = acc * sg;
}

// ================= bcdt = xc @ xw, xw staged in smem =================
__global__ __launch_bounds__(256) void bcdt_kernel(
    const float* __restrict__ xc, const float* __restrict__ xw0,
    const float* __restrict__ xw1, float* __restrict__ bcdt)
{
    __shared__ float sw[256 * NX];   // 33 KB
    int dir  = blockIdx.z;
    int warp = threadIdx.x >> 5;
    int lane = threadIdx.x & 31;
    int tok  = blockIdx.x * 8 + warp;
    const float* xw = dir ? xw1 : xw0;
    const float* xr = xc + (size_t)dir * TOK * DI + (size_t)tok * DI;
    float acc = 0.f, acc32 = 0.f;
    for (int kc = 0; kc < DI; kc += 256) {
        __syncthreads();
        for (int i = threadIdx.x; i < 256 * NX; i += 256)
            sw[i] = xw[(size_t)kc * NX + i];
        __syncthreads();
        #pragma unroll 4
        for (int k = 0; k < 256; k += 4) {
            float4 xv = *reinterpret_cast<const float4*>(xr + kc + k);
            const float* wr = sw + k * NX;
            acc = fmaf(xv.x, wr[lane],          acc);
            acc = fmaf(xv.y, wr[NX + lane],     acc);
            acc = fmaf(xv.z, wr[2 * NX + lane], acc);
            acc = fmaf(xv.w, wr[3 * NX + lane], acc);
            if (lane == 0) {
                acc32 = fmaf(xv.x, wr[32],          acc32);
                acc32 = fmaf(xv.y, wr[NX + 32],     acc32);
                acc32 = fmaf(xv.z, wr[2 * NX + 32], acc32);
                acc32 = fmaf(xv.w, wr[3 * NX + 32], acc32);
            }
        }
    }
    float* orow = bcdt + ((size_t)dir * TOK + tok) * NX;
    orow[lane] = acc;
    if (lane == 0) orow[32] = acc32;
}

// ================= dt = softplus(...); u = dt*xc =================
__global__ __launch_bounds__(256) void dtu_kernel(
    const float* __restrict__ bcdt, const float* __restrict__ xc,
    const float* __restrict__ dtw0, const float* __restrict__ dtw1,
    const float* __restrict__ dtb0, const float* __restrict__ dtb1,
    float* __restrict__ dt, float* __restrict__ u)
{
    int dir = blockIdx.z;
    int idx = blockIdx.x * blockDim.x + threadIdx.x;
    if (idx >= TOK * DI) return;
    int tok = idx / DI;
    int d   = idx - tok * DI;
    float draw = bcdt[((size_t)dir * TOK + tok) * NX];
    float pre = fmaf(draw, (dir ? dtw1 : dtw0)[d], (dir ? dtb1 : dtb0)[d]);
    float dtv = (pre > 20.f) ? pre : log1pf(expf(pre));
    size_t o = (size_t)dir * TOK * DI + idx;
    dt[o] = dtv;
    u[o]  = dtv * xc[o];
}

// ================= selective scan =================
__global__ __launch_bounds__(256) void scan_kernel(
    const float* __restrict__ bcdt, const float* __restrict__ dt,
    const float* __restrict__ u, const float* __restrict__ Alog0,
    const float* __restrict__ Alog1, float* __restrict__ ys)
{
    int wg   = (blockIdx.x * blockDim.x + threadIdx.x) >> 5;  // 0..3071
    int lane = threadIdx.x & 31;
    int dir  = wg / 1536;
    int rem  = wg - dir * 1536;
    int b    = rem / 768;
    int wp   = rem - b * 768;
    int half = lane >> 4;
    int s    = lane & 15;
    int d    = wp * 2 + half;

    const float* Alog = dir ? Alog1 : Alog0;
    float al = Alog[d * NSTATE + s];
    al = fminf(fmaxf(al, -6.f), 6.f);
    float Aval = -__expf(al);

    size_t tokBase = (size_t)dir * TOK + (size_t)b * SEQ;
    const float* dtp  = dt   + tokBase * DI + d;
    const float* up   = u    + tokBase * DI + d;
    const float* rowp = bcdt + tokBase * NX;
    float* ysp        = ys   + tokBase * DI + d;

    float h = 0.f;
    float dtv = *dtp, uv = *up;
    float Bv = rowp[1 + s], Cv = rowp[17 + s];

    for (int t = 0; t < SEQ; ++t) {
        float a = __expf(dtv * Aval);
        float hb = fmaf(a, h, uv * Bv);
        hb = fminf(fmaxf(hb, -10000.f), 10000.f);
        h = hb;
        float p = h * Cv;
        if (t < SEQ - 1) {
            dtp += DI; up += DI; rowp += NX;
            dtv = *dtp; uv = *up;
            Bv = rowp[1 + s]; Cv = rowp[17 + s];
        }
        p += __shfl_xor_sync(0xffffffffu, p, 8);
        p += __shfl_xor_sync(0xffffffffu, p, 4);
        p += __shfl_xor_sync(0xffffffffu, p, 2);
        p += __shfl_xor_sync(0xffffffffu, p, 1);
        if (s == 0) *ysp = p;
        ysp += DI;
    }
}

// ================= gate: g = (ys + xc*Dp) * silu(z) -> bf16 hi/lo ==========
__global__ __launch_bounds__(256) void gate_kernel(
    const float* __restrict__ ys, const float* __restrict__ xc,
    const float* __restrict__ xz, const float* __restrict__ Dp0,
    const float* __restrict__ Dp1, bf16* __restrict__ gh, bf16* __restrict__ gl)
{
    int dir = blockIdx.z;
    int idx = blockIdx.x * blockDim.x + threadIdx.x;
    if (idx >= TOK * DI) return;
    int tok = idx / DI;
    int d   = idx - tok * DI;
    size_t o = (size_t)dir * TOK * DI + idx;
    float z = xz[(size_t)dir * TOK * DI2 + (size_t)tok * DI2 + DI + d];
    float sz = z / (1.f + __expf(-z));
    float y = fmaf(xc[o], (dir ? Dp1 : Dp0)[d], ys[o]);
    float v = y * sz;
    bf16 h = __float2bfloat16(v);
    gh[o] = h;
    gl[o] = __float2bfloat16(v - __bfloat162float(h));
}

// ================= combine =================
__global__ __launch_bounds__(256) void combine_kernel(
    const float* __restrict__ x, const float* __restrict__ alpha,
    const float* __restrict__ yp, float* __restrict__ out)
{
    int idx = blockIdx.x * blockDim.x + threadIdx.x;
    if (idx >= TOK * DM) return;
    int tok = idx / DM;
    int m   = idx - tok * DM;
    float a = 1.f / (1.f + __expf(-alpha[0]));
    int tokb = tok ^ (SEQ - 1);
    float yf = yp[idx];
    float yb = yp[(size_t)TOK * DM + (size_t)tokb * DM + m];
    out[idx] = fmaf(a, yf, fmaf(1.f - a, yb, x[idx]));
}

// ================= launch =================
extern "C" void kernel_launch(void* const* d_in, const int* in_sizes, int n_in,
                              void* d_out, int out_size)
{
    const float* x     = (const float*)d_in[0];
    const float* ln_g  = (const float*)d_in[1];
    const float* ln_b  = (const float*)d_in[2];
    const float* alpha = (const float*)d_in[3];
    const float* f_inw  = (const float*)d_in[4];
    const float* f_cw   = (const float*)d_in[5];
    const float* f_cb   = (const float*)d_in[6];
    const float* f_xw   = (const float*)d_in[7];
    const float* f_dtw  = (const float*)d_in[8];
    const float* f_dtb  = (const float*)d_in[9];
    const float* f_Alog = (const float*)d_in[10];
    const float* f_D    = (const float*)d_in[11];
    const float* f_outw = (const float*)d_in[12];
    const float* b_inw  = (const float*)d_in[13];
    const float* b_cw   = (const float*)d_in[14];
    const float* b_cb   = (const float*)d_in[15];
    const float* b_xw   = (const float*)d_in[16];
    const float* b_dtw  = (const float*)d_in[17];
    const float* b_dtb  = (const float*)d_in[18];
    const float* b_Alog = (const float*)d_in[19];
    const float* b_D    = (const float*)d_in[20];
    const float* b_outw = (const float*)d_in[21];
    float* out = (float*)d_out;

    bf16 *xnh, *xnl, *winh, *winl, *wouth, *woutl, *gh, *gl;
    float *xz, *xc, *bcdt, *dt, *u, *ys, *yp;
    cudaGetSymbolAddress((void**)&xnh,   g_xn_h);
    cudaGetSymbolAddress((void**)&xnl,   g_xn_l);
    cudaGetSymbolAddress((void**)&winh,  g_win_h);
    cudaGetSymbolAddress((void**)&winl,  g_win_l);
    cudaGetSymbolAddress((void**)&wouth, g_wout_h);
    cudaGetSymbolAddress((void**)&woutl, g_wout_l);
    cudaGetSymbolAddress((void**)&gh,    g_g_h);
    cudaGetSymbolAddress((void**)&gl,    g_g_l);
    cudaGetSymbolAddress((void**)&xz,    g_xz);
    cudaGetSymbolAddress((void**)&xc,    g_xc);
    cudaGetSymbolAddress((void**)&bcdt,  g_bcdt);
    cudaGetSymbolAddress((void**)&dt,    g_dt);
    cudaGetSymbolAddress((void**)&u,     g_u);
    cudaGetSymbolAddress((void**)&ys,    g_ys);
    cudaGetSymbolAddress((void**)&yp,    g_yp);

    const int smemGemm = 2 * STAGE_B;   // 128 KB double-buffered
    cudaFuncSetAttribute(mma_gemm, cudaFuncAttributeMaxDynamicSharedMemorySize, smemGemm);

    // 1) layernorm -> bf16 hi/lo
    ln_kernel<<<TOK, 256>>>(x, ln_g, ln_b, xnh, xnl);

    // 2) weight transpose + split (both dirs)
    wsplit_kernel<<<dim3(DI2 / 32, DM / 32, 2), dim3(32, 8)>>>(
        f_inw, b_inw, winh, winl, DM, DI2);
    wsplit_kernel<<<dim3(DM / 32, DI / 32, 2), dim3(32, 8)>>>(
        f_outw, b_outw, wouth, woutl, DI, DM);

    // 3) in-proj GEMM (mma.sync bf16x3); dir 1 reads time-flipped rows
    mma_gemm<<<dim3(DI2 / 128, TOK / 128, 2), 256, smemGemm>>>(
        xnh, xnl, winh, winl, xz, TOK, DI2, DM, /*aPerDir=*/0, /*flipA=*/1);

    // 4) depthwise conv + SiLU
    conv_silu_kernel<<<dim3((TOK * DI) / 256, 1, 2), 256>>>(
        xz, f_cw, b_cw, f_cb, b_cb, xc);

    // 5) bcdt
    bcdt_kernel<<<dim3(TOK / 8, 1, 2), 256>>>(xc, f_xw, b_xw, bcdt);

    // 6) dt/u precompute
    dtu_kernel<<<dim3((TOK * DI) / 256, 1, 2), 256>>>(
        bcdt, xc, f_dtw, b_dtw, f_dtb, b_dtb, dt, u);

    // 7) selective scan
    scan_kernel<<<384, 256>>>(bcdt, dt, u, f_Alog, b_Alog, ys);

    // 8) gate -> bf16 hi/lo
    gate_kernel<<<dim3((TOK * DI) / 256, 1, 2), 256>>>(
        ys, xc, xz, f_D, b_D, gh, gl);

    // 9) out-proj GEMM (mma.sync bf16x3)
    mma_gemm<<<dim3(DM / 128, TOK / 128, 2), 256, smemGemm>>>(
        gh, gl, wouth, woutl, yp, TOK, DM, DI, /*aPerDir=*/1, /*flipA=*/0);

    // 10) combine + residual
    combine_kernel<<<(TOK * DM) / 256, 256>>>(x, alpha, yp, out);
}